// round 1
// baseline (speedup 1.0000x reference)
#include <cuda_runtime.h>
#include <cstdint>

// Problem constants (n=1, C=256, t=8, h=64, w=64, heads=8)
#define HEADS 8
#define TT 8
#define HH 64
#define WW 64
#define SDIM (TT + HH + WW - 2)   // 134
#define SP (TT * HH * WW)          // 32768 spatial elements
#define PLANE (HH * WW)            // 4096
#define CDIM 256
#define CG (CDIM / HEADS)          // 32 channels per head

#define PV_STRIDE 1025             // 64*16 + 1 pad (bank-conflict-free for ch split)

// Scratch for pv = conv(value)  (static __device__ allocation: allowed)
__device__ float g_pv[CDIM * SP];

using ull = unsigned long long;

__device__ __forceinline__ ull packf2(float lo, float hi) {
    ull r;
    asm("mov.b64 %0, {%1, %2};" : "=l"(r) : "f"(lo), "f"(hi));
    return r;
}
__device__ __forceinline__ void unpackf2(ull v, float& lo, float& hi) {
    asm("mov.b64 {%0, %1}, %2;" : "=f"(lo), "=f"(hi) : "l"(v));
}
__device__ __forceinline__ void ffma2(ull& d, ull a, ull b) {
    asm("fma.rn.f32x2 %0, %1, %2, %3;" : "=l"(d) : "l"(a), "l"(b), "l"(d));
}

// ---------------------------------------------------------------------------
// Kernel 1: pv[o, s] = bias[o] + sum_c W[o, c] * V[c, s]
// BM=64 (o), BN=256 (s), BK=16. 256 threads, 8x8 per thread, f32x2 FMA.
// Thread's s columns: {tx*4 .. tx*4+3} and {128+tx*4 .. 128+tx*4+3}
// ---------------------------------------------------------------------------
__global__ void __launch_bounds__(256) conv_gemm_kernel(
    const float* __restrict__ V, const float* __restrict__ Wm,
    const float* __restrict__ bias)
{
    __shared__ float Ws[16][64];    // [k][o]
    __shared__ float Vs[16][256];   // [k][s]

    const int tid = threadIdx.x;
    const int tx = tid & 31;
    const int ty = tid >> 5;        // 0..7
    const int oBase = blockIdx.y * 64;
    const int sBase = blockIdx.x * 256;

    ull acc[8][4];
    #pragma unroll
    for (int i = 0; i < 8; ++i) {
        float bv = bias[oBase + ty * 8 + i];
        ull pb = packf2(bv, bv);
        #pragma unroll
        for (int j = 0; j < 4; ++j) acc[i][j] = pb;
    }

    for (int kk = 0; kk < CDIM; kk += 16) {
        // Load W tile (64 o x 16 k), store transposed
        {
            const int oo = tid >> 2;
            const int kb = (tid & 3) * 4;
            float4 wv = *(const float4*)&Wm[(oBase + oo) * CDIM + kk + kb];
            Ws[kb + 0][oo] = wv.x;
            Ws[kb + 1][oo] = wv.y;
            Ws[kb + 2][oo] = wv.z;
            Ws[kb + 3][oo] = wv.w;
        }
        // Load V tile (16 k x 256 s)
        #pragma unroll
        for (int j = 0; j < 4; ++j) {
            int idx = tid + j * 256;
            int r = idx >> 6, c4 = idx & 63;
            *(float4*)&Vs[r][c4 * 4] =
                *(const float4*)&V[(kk + r) * SP + sBase + c4 * 4];
        }
        __syncthreads();

        #pragma unroll
        for (int k = 0; k < 16; ++k) {
            float4 b0 = *(const float4*)&Vs[k][tx * 4];          // s = tx*4..+3
            float4 b1 = *(const float4*)&Vs[k][128 + tx * 4];    // s = 128+tx*4..+3
            ull bb0 = packf2(b0.x, b0.y);
            ull bb1 = packf2(b0.z, b0.w);
            ull bb2 = packf2(b1.x, b1.y);
            ull bb3 = packf2(b1.z, b1.w);
            #pragma unroll
            for (int i = 0; i < 8; ++i) {
                float a = Ws[k][ty * 8 + i];   // warp-uniform broadcast
                ull a2 = packf2(a, a);
                ffma2(acc[i][0], a2, bb0);
                ffma2(acc[i][1], a2, bb1);
                ffma2(acc[i][2], a2, bb2);
                ffma2(acc[i][3], a2, bb3);
            }
        }
        __syncthreads();
    }

    // Store
    #pragma unroll
    for (int i = 0; i < 8; ++i) {
        float r0, r1, r2, r3, r4, r5, r6, r7;
        unpackf2(acc[i][0], r0, r1);
        unpackf2(acc[i][1], r2, r3);
        unpackf2(acc[i][2], r4, r5);
        unpackf2(acc[i][3], r6, r7);
        float* dst = &g_pv[(oBase + ty * 8 + i) * SP + sBase];
        float4 v0 = {r0, r1, r2, r3};
        float4 v1 = {r4, r5, r6, r7};
        *(float4*)&dst[tx * 4] = v0;
        *(float4*)&dst[128 + tx * 4] = v1;
    }
}

// ---------------------------------------------------------------------------
// Kernel 2: t-sum + h-sum, writes out.
// Block: (x-tile of 16, tau, head). 512 threads.
// Thread: x = tid&15, ch = (tid>>4)&1 (c half), qg = tid>>5 (4 q's).
// smem: pvs[32c][64p][16x] (stride 1025) + At_s[8s][64q][16x]
// ---------------------------------------------------------------------------
__global__ void __launch_bounds__(512) attn_th_kernel(
    const float* __restrict__ A, float* __restrict__ out)
{
    extern __shared__ float smem[];
    float* pvs = smem;                       // 32 * PV_STRIDE floats
    float* At_s = smem + 32 * PV_STRIDE;     // 8*64*16 floats

    const int tid = threadIdx.x;
    const int x = tid & 15;
    const int ch = (tid >> 4) & 1;
    const int qg = tid >> 5;                 // 0..15
    const int x0 = blockIdx.x * 16;
    const int tau = blockIdx.y;
    const int b = blockIdx.z;
    const int cbase = b * CG;
    const int attb = b * SDIM * SP;

    // Load pv plane slice [32c][64p][16x]
    for (int i = tid; i < 32 * 64 * 4; i += 512) {
        int row = i >> 2, f4 = i & 3;
        int c = row >> 6, p = row & 63;
        float4 v = *(const float4*)&g_pv[(cbase + c) * SP + tau * PLANE + p * 64 + x0 + f4 * 4];
        float* dstp = &pvs[c * PV_STRIDE + p * 16 + f4 * 4];
        dstp[0] = v.x; dstp[1] = v.y; dstp[2] = v.z; dstp[3] = v.w;
    }
    // Load A_t slice [8s][64q][16x]
    for (int i = tid; i < 8 * 64 * 16; i += 512) {
        int xr = i & 15, q = (i >> 4) & 63, s = i >> 10;
        At_s[i] = A[attb + s * SP + tau * PLANE + q * 64 + x0 + xr];
    }
    __syncthreads();

    float acc[16][4];
    #pragma unroll
    for (int ci = 0; ci < 16; ++ci)
        #pragma unroll
        for (int qi = 0; qi < 4; ++qi) acc[ci][qi] = 0.0f;

    const int qb = qg * 4;
    const float* Ah = A + attb + TT * SP + tau * PLANE + x0 + x;  // + j*SP + q*64

    // h-sum: out[c,q,x] += A_h_full[p -> q at (tau,q,x)] * pv[c,tau,p,x]
    #pragma unroll 2
    for (int p = 0; p < 64; ++p) {
        float av[4];
        #pragma unroll
        for (int qi = 0; qi < 4; ++qi) {
            int q = qb + qi;
            int j = (p < q) ? p : (p - 1);
            av[qi] = (p == q) ? 0.0f : __ldg(&Ah[j * SP + q * 64]);
        }
        float pvv[16];
        #pragma unroll
        for (int ci = 0; ci < 16; ++ci)
            pvv[ci] = pvs[(ch * 16 + ci) * PV_STRIDE + p * 16 + x];
        #pragma unroll
        for (int qi = 0; qi < 4; ++qi)
            #pragma unroll
            for (int ci = 0; ci < 16; ++ci)
                acc[ci][qi] = fmaf(av[qi], pvv[ci], acc[ci][qi]);
    }

    // t-sum: out[c,q,x] += A_t[s,tau,q,x] * pv[c,s,q,x]
    #pragma unroll 1
    for (int s = 0; s < 8; ++s) {
        #pragma unroll
        for (int qi = 0; qi < 4; ++qi) {
            int q = qb + qi;
            float at = At_s[(s * 64 + q) * 16 + x];
            const float* pg = &g_pv[(cbase + ch * 16) * SP + s * PLANE + q * 64 + x0 + x];
            #pragma unroll
            for (int ci = 0; ci < 16; ++ci)
                acc[ci][qi] = fmaf(at, __ldg(&pg[ci * SP]), acc[ci][qi]);
        }
    }

    // Write out (full overwrite)
    #pragma unroll
    for (int qi = 0; qi < 4; ++qi) {
        int q = qb + qi;
        #pragma unroll
        for (int ci = 0; ci < 16; ++ci)
            out[(cbase + ch * 16 + ci) * SP + tau * PLANE + q * 64 + x0 + x] = acc[ci][qi];
    }
}

// ---------------------------------------------------------------------------
// Kernel 3: w-sum, accumulates into out (RMW).
// Block: (q-tile of 16, tau, head). 512 threads.
// Thread: xg = tid&15, ch = (tid>>4)&1, qloc = tid>>5. x = xg + 16*xi.
// smem: pvw[32c][16q][64p] (stride 1025)
// ---------------------------------------------------------------------------
__global__ void __launch_bounds__(512) attn_w_kernel(
    const float* __restrict__ A, float* __restrict__ out)
{
    extern __shared__ float smem[];
    float* pvw = smem;   // 32 * PV_STRIDE floats

    const int tid = threadIdx.x;
    const int xg = tid & 15;
    const int ch = (tid >> 4) & 1;
    const int qloc = tid >> 5;   // 0..15
    const int q0 = blockIdx.x * 16;
    const int tau = blockIdx.y;
    const int b = blockIdx.z;
    const int cbase = b * CG;
    const int attb = b * SDIM * SP;
    const int q = q0 + qloc;

    // Load pv row slice [32c][16q][64p]
    for (int i = tid; i < 32 * 16 * 16; i += 512) {
        int row = i >> 4, f4 = i & 15;
        int c = row >> 4, qi = row & 15;
        float4 v = *(const float4*)&g_pv[(cbase + c) * SP + tau * PLANE + (q0 + qi) * 64 + f4 * 4];
        float* dstp = &pvw[c * PV_STRIDE + qi * 64 + f4 * 4];
        dstp[0] = v.x; dstp[1] = v.y; dstp[2] = v.z; dstp[3] = v.w;
    }
    __syncthreads();

    float acc[16][4];
    #pragma unroll
    for (int ci = 0; ci < 16; ++ci)
        #pragma unroll
        for (int xi = 0; xi < 4; ++xi) acc[ci][xi] = 0.0f;

    const float* Aw = A + attb + (TT + HH - 1) * SP + tau * PLANE + q * 64;  // + j*SP + x

    // w-sum: out[c,q,x] += A_w_full[p -> x at (tau,q,x)] * pv[c,tau,q,p]
    #pragma unroll 2
    for (int p = 0; p < 64; ++p) {
        float av[4];
        #pragma unroll
        for (int xi = 0; xi < 4; ++xi) {
            int xx = xg + 16 * xi;
            int j = (p < xx) ? p : (p - 1);
            av[xi] = (p == xx) ? 0.0f : __ldg(&Aw[j * SP + xx]);
        }
        float pvv[16];
        #pragma unroll
        for (int ci = 0; ci < 16; ++ci)
            pvv[ci] = pvw[(ch * 16 + ci) * PV_STRIDE + qloc * 64 + p];
        #pragma unroll
        for (int xi = 0; xi < 4; ++xi)
            #pragma unroll
            for (int ci = 0; ci < 16; ++ci)
                acc[ci][xi] = fmaf(av[xi], pvv[ci], acc[ci][xi]);
    }

    // Accumulate into out
    #pragma unroll
    for (int xi = 0; xi < 4; ++xi) {
        #pragma unroll
        for (int ci = 0; ci < 16; ++ci) {
            int idx = (cbase + ch * 16 + ci) * SP + tau * PLANE + q * 64 + xg + 16 * xi;
            out[idx] += acc[ci][xi];
        }
    }
}

// ---------------------------------------------------------------------------

extern "C" void kernel_launch(void* const* d_in, const int* in_sizes, int n_in,
                              void* d_out, int out_size) {
    (void)in_sizes; (void)n_in; (void)out_size;
    const float* A    = (const float*)d_in[0];   // attention [1,1072,8,64,64]
    const float* V    = (const float*)d_in[1];   // value [1,256,8,64,64]
    const float* Wm   = (const float*)d_in[2];   // conv_w [256,256]
    const float* bias = (const float*)d_in[3];   // conv_b [256]
    float* out = (float*)d_out;

    const int SMEM_TH = (32 * PV_STRIDE + 8 * 64 * 16) * (int)sizeof(float); // 163968
    const int SMEM_W  = (32 * PV_STRIDE) * (int)sizeof(float);               // 131200

    cudaFuncSetAttribute(attn_th_kernel, cudaFuncAttributeMaxDynamicSharedMemorySize, SMEM_TH);
    cudaFuncSetAttribute(attn_w_kernel,  cudaFuncAttributeMaxDynamicSharedMemorySize, SMEM_W);

    conv_gemm_kernel<<<dim3(SP / 256, CDIM / 64), 256>>>(V, Wm, bias);
    attn_th_kernel<<<dim3(4, TT, HEADS), 512, SMEM_TH>>>(A, out);
    attn_w_kernel<<<dim3(4, TT, HEADS), 512, SMEM_W>>>(A, out);
}

// round 2
// speedup vs baseline: 1.0142x; 1.0142x over previous
#include <cuda_runtime.h>
#include <cstdint>

// Problem constants (n=1, C=256, t=8, h=64, w=64, heads=8)
#define HEADS 8
#define TT 8
#define HH 64
#define WW 64
#define SDIM (TT + HH + WW - 2)   // 134
#define SP (TT * HH * WW)          // 32768
#define PLANE (HH * WW)            // 4096
#define CDIM 256
#define CG (CDIM / HEADS)          // 32 channels per head

// Scratch for pv = conv(value)
__device__ float g_pv[CDIM * SP];

using ull = unsigned long long;

__device__ __forceinline__ ull packf2(float lo, float hi) {
    ull r;
    asm("mov.b64 %0, {%1, %2};" : "=l"(r) : "f"(lo), "f"(hi));
    return r;
}
__device__ __forceinline__ void unpackf2(ull v, float& lo, float& hi) {
    asm("mov.b64 {%0, %1}, %2;" : "=f"(lo), "=f"(hi) : "l"(v));
}
__device__ __forceinline__ void ffma2(ull& d, ull a, ull b) {
    asm("fma.rn.f32x2 %0, %1, %2, %3;" : "=l"(d) : "l"(a), "l"(b), "l"(d));
}

// ---------------------------------------------------------------------------
// Kernel 1: pv[o, s] = bias[o] + sum_c W[o, c] * V[c, s]
// BM=32 (o), BN=256 (s), BK=16. 256 threads, 4o x 8s per thread (f32x2).
// Register-prefetch pipeline over the k tiles; W stored duplicated as float2
// so the a-operand is one LDS.64 broadcast.
// ---------------------------------------------------------------------------
__global__ void __launch_bounds__(256) conv_gemm_kernel(
    const float* __restrict__ V, const float* __restrict__ Wm,
    const float* __restrict__ bias)
{
    __shared__ float2 Ws2[16][32];  // [k][o], duplicated
    __shared__ float Vs[16][256];   // [k][s]

    const int tid = threadIdx.x;
    const int tx = tid & 31;
    const int ty = tid >> 5;        // 0..7
    const int oBase = blockIdx.y * 32;
    const int sBase = blockIdx.x * 256;

    ull acc[4][4];
    #pragma unroll
    for (int i = 0; i < 4; ++i) {
        float bv = bias[oBase + ty * 4 + i];
        ull pb = packf2(bv, bv);
        #pragma unroll
        for (int j = 0; j < 4; ++j) acc[i][j] = pb;
    }

    // prefetch registers
    float4 wv;      // valid for tid < 128
    float4 vv[4];

    const int oo = tid >> 2;        // 0..63 (use <32 rows: tid<128)
    const int kb = (tid & 3) * 4;

    // load first tile into regs
    if (tid < 128) wv = *(const float4*)&Wm[(oBase + oo) * CDIM + 0 + kb];
    #pragma unroll
    for (int j = 0; j < 4; ++j) {
        int idx = tid + j * 256;
        int r = idx >> 6, c4 = idx & 63;
        vv[j] = *(const float4*)&V[(0 + r) * SP + sBase + c4 * 4];
    }

    for (int kk = 0; kk < CDIM; kk += 16) {
        __syncthreads();
        // store prefetched tile
        if (tid < 128) {
            Ws2[kb + 0][oo] = make_float2(wv.x, wv.x);
            Ws2[kb + 1][oo] = make_float2(wv.y, wv.y);
            Ws2[kb + 2][oo] = make_float2(wv.z, wv.z);
            Ws2[kb + 3][oo] = make_float2(wv.w, wv.w);
        }
        #pragma unroll
        for (int j = 0; j < 4; ++j) {
            int idx = tid + j * 256;
            int r = idx >> 6, c4 = idx & 63;
            *(float4*)&Vs[r][c4 * 4] = vv[j];
        }
        __syncthreads();

        // prefetch next tile
        int kn = kk + 16;
        if (kn < CDIM) {
            if (tid < 128) wv = *(const float4*)&Wm[(oBase + oo) * CDIM + kn + kb];
            #pragma unroll
            for (int j = 0; j < 4; ++j) {
                int idx = tid + j * 256;
                int r = idx >> 6, c4 = idx & 63;
                vv[j] = *(const float4*)&V[(kn + r) * SP + sBase + c4 * 4];
            }
        }

        #pragma unroll
        for (int k = 0; k < 16; ++k) {
            float4 b0 = *(const float4*)&Vs[k][tx * 4];
            float4 b1 = *(const float4*)&Vs[k][128 + tx * 4];
            ull bb0 = packf2(b0.x, b0.y);
            ull bb1 = packf2(b0.z, b0.w);
            ull bb2 = packf2(b1.x, b1.y);
            ull bb3 = packf2(b1.z, b1.w);
            #pragma unroll
            for (int i = 0; i < 4; ++i) {
                ull a2 = *reinterpret_cast<const ull*>(&Ws2[k][ty * 4 + i]);
                ffma2(acc[i][0], a2, bb0);
                ffma2(acc[i][1], a2, bb1);
                ffma2(acc[i][2], a2, bb2);
                ffma2(acc[i][3], a2, bb3);
            }
        }
    }

    #pragma unroll
    for (int i = 0; i < 4; ++i) {
        float r0, r1, r2, r3, r4, r5, r6, r7;
        unpackf2(acc[i][0], r0, r1);
        unpackf2(acc[i][1], r2, r3);
        unpackf2(acc[i][2], r4, r5);
        unpackf2(acc[i][3], r6, r7);
        float* dst = &g_pv[(oBase + ty * 4 + i) * SP + sBase];
        float4 v0 = {r0, r1, r2, r3};
        float4 v1 = {r4, r5, r6, r7};
        *(float4*)&dst[tx * 4] = v0;
        *(float4*)&dst[128 + tx * 4] = v1;
    }
}

// ---------------------------------------------------------------------------
// Kernel 2: t-sum. out[c,tau,pos] = sum_s A_t[s,tau,pos] * pv[c,s,pos]
// Block: (plane chunk of 128, head). 512 threads.
// Thread: pos = tid&127, cg = tid>>7 (8 channels each). pv in registers
// (each pv element read from DRAM exactly once); A_t staged in smem.
// Writes out (overwrite).
// ---------------------------------------------------------------------------
__global__ void __launch_bounds__(512) attn_t_kernel(
    const float* __restrict__ A, float* __restrict__ out)
{
    __shared__ float ats[8 * 8 * 128];   // [s][tau][pos] 32KB

    const int tid = threadIdx.x;
    const int pos = tid & 127;
    const int cg = tid >> 7;             // 0..3
    const int pos0 = blockIdx.x * 128;
    const int b = blockIdx.y;
    const int cbase = b * CG;
    const int attb = b * SDIM * SP;

    // stage A_t [8s][8tau][128pos]
    for (int i = tid; i < 8192; i += 512) {
        int p_i = i & 127, tau_i = (i >> 7) & 7, s_i = i >> 10;
        ats[i] = A[attb + s_i * SP + tau_i * PLANE + pos0 + p_i];
    }

    // pv into registers: [8s][4 channel-pairs]
    ull pvr[8][4];
    #pragma unroll
    for (int s = 0; s < 8; ++s)
        #pragma unroll
        for (int cp = 0; cp < 4; ++cp) {
            const float* g = &g_pv[(cbase + cg * 8 + 2 * cp) * SP + s * PLANE + pos0 + pos];
            pvr[s][cp] = packf2(g[0], g[SP]);
        }
    __syncthreads();

    ull z = packf2(0.0f, 0.0f);
    #pragma unroll 1
    for (int tau = 0; tau < 8; ++tau) {
        ull acc[4] = {z, z, z, z};
        #pragma unroll
        for (int s = 0; s < 8; ++s) {
            float at = ats[(s * 8 + tau) * 128 + pos];
            ull a2 = packf2(at, at);
            #pragma unroll
            for (int cp = 0; cp < 4; ++cp)
                ffma2(acc[cp], a2, pvr[s][cp]);
        }
        #pragma unroll
        for (int cp = 0; cp < 4; ++cp) {
            float lo, hi;
            unpackf2(acc[cp], lo, hi);
            float* o = &out[(cbase + cg * 8 + 2 * cp) * SP + tau * PLANE + pos0 + pos];
            o[0] = lo;
            o[SP] = hi;
        }
    }
}

// ---------------------------------------------------------------------------
// Kernel 3: h-sum, RMW into out.
// Block: (x-tile of 16, tau, head). 512 threads.
// smem pv as channel-pair float2: [cp=16][p=64][x=16]
// ---------------------------------------------------------------------------
__global__ void __launch_bounds__(512) attn_h_kernel(
    const float* __restrict__ A, float* __restrict__ out)
{
    extern __shared__ float2 pv2[];   // 16*64*16 float2 = 128KB

    const int tid = threadIdx.x;
    const int x = tid & 15;
    const int ch = (tid >> 4) & 1;
    const int qg = tid >> 5;          // 0..15
    const int x0 = blockIdx.x * 16;
    const int tau = blockIdx.y;
    const int b = blockIdx.z;
    const int cbase = b * CG;
    const int attb = b * SDIM * SP;

    for (int i = tid; i < 16 * 64 * 16; i += 512) {
        int xi = i & 15, p = (i >> 4) & 63, cp = i >> 10;
        const float* g = &g_pv[(cbase + 2 * cp) * SP + tau * PLANE + p * 64 + x0 + xi];
        pv2[i] = make_float2(g[0], g[SP]);
    }
    __syncthreads();

    ull z = packf2(0.0f, 0.0f);
    ull acc[4][8];
    #pragma unroll
    for (int qi = 0; qi < 4; ++qi)
        #pragma unroll
        for (int cp = 0; cp < 8; ++cp) acc[qi][cp] = z;

    const int qb = qg * 4;
    const float* Ah = A + attb + TT * SP + tau * PLANE + x0 + x;  // + j*SP + q*64

    #pragma unroll 2
    for (int p = 0; p < 64; ++p) {
        ull a2[4];
        #pragma unroll
        for (int qi = 0; qi < 4; ++qi) {
            int q = qb + qi;
            int j = (p < q) ? p : (p - 1);
            float av = (p == q) ? 0.0f : __ldg(&Ah[j * SP + q * 64]);
            a2[qi] = packf2(av, av);
        }
        ull pp[8];
        #pragma unroll
        for (int cp = 0; cp < 8; ++cp)
            pp[cp] = *reinterpret_cast<const ull*>(&pv2[((ch * 8 + cp) * 64 + p) * 16 + x]);
        #pragma unroll
        for (int qi = 0; qi < 4; ++qi)
            #pragma unroll
            for (int cp = 0; cp < 8; ++cp)
                ffma2(acc[qi][cp], a2[qi], pp[cp]);
    }

    #pragma unroll
    for (int qi = 0; qi < 4; ++qi) {
        int q = qb + qi;
        #pragma unroll
        for (int cp = 0; cp < 8; ++cp) {
            float lo, hi;
            unpackf2(acc[qi][cp], lo, hi);
            float* o = &out[(cbase + ch * 16 + 2 * cp) * SP + tau * PLANE + q * 64 + x0 + x];
            o[0] += lo;
            o[SP] += hi;
        }
    }
}

// ---------------------------------------------------------------------------
// Kernel 4: w-sum, RMW into out.
// Block: (q-tile of 16, tau, head). 512 threads.
// smem pv as channel-pair float2: [cp=16][q=16][p=64]
// ---------------------------------------------------------------------------
__global__ void __launch_bounds__(512) attn_w_kernel(
    const float* __restrict__ A, float* __restrict__ out)
{
    extern __shared__ float2 pw2[];   // 16*16*64 float2 = 128KB

    const int tid = threadIdx.x;
    const int xg = tid & 15;
    const int ch = (tid >> 4) & 1;
    const int qloc = tid >> 5;        // 0..15
    const int q0 = blockIdx.x * 16;
    const int tau = blockIdx.y;
    const int b = blockIdx.z;
    const int cbase = b * CG;
    const int attb = b * SDIM * SP;
    const int q = q0 + qloc;

    for (int i = tid; i < 16 * 16 * 64; i += 512) {
        int p = i & 63, qi = (i >> 6) & 15, cp = i >> 10;
        const float* g = &g_pv[(cbase + 2 * cp) * SP + tau * PLANE + (q0 + qi) * 64 + p];
        pw2[i] = make_float2(g[0], g[SP]);
    }
    __syncthreads();

    ull z = packf2(0.0f, 0.0f);
    ull acc[4][8];
    #pragma unroll
    for (int xi = 0; xi < 4; ++xi)
        #pragma unroll
        for (int cp = 0; cp < 8; ++cp) acc[xi][cp] = z;

    const float* Aw = A + attb + (TT + HH - 1) * SP + tau * PLANE + q * 64;  // + j*SP + x

    #pragma unroll 2
    for (int p = 0; p < 64; ++p) {
        ull a2[4];
        #pragma unroll
        for (int xi = 0; xi < 4; ++xi) {
            int xx = xg + 16 * xi;
            int j = (p < xx) ? p : (p - 1);
            float av = (p == xx) ? 0.0f : __ldg(&Aw[j * SP + xx]);
            a2[xi] = packf2(av, av);
        }
        ull pp[8];
        #pragma unroll
        for (int cp = 0; cp < 8; ++cp)
            pp[cp] = *reinterpret_cast<const ull*>(&pw2[((ch * 8 + cp) * 16 + qloc) * 64 + p]);
        #pragma unroll
        for (int xi = 0; xi < 4; ++xi)
            #pragma unroll
            for (int cp = 0; cp < 8; ++cp)
                ffma2(acc[xi][cp], a2[xi], pp[cp]);
    }

    #pragma unroll
    for (int xi = 0; xi < 4; ++xi) {
        #pragma unroll
        for (int cp = 0; cp < 8; ++cp) {
            float lo, hi;
            unpackf2(acc[xi][cp], lo, hi);
            float* o = &out[(cbase + ch * 16 + 2 * cp) * SP + tau * PLANE + q * 64 + xg + 16 * xi];
            o[0] += lo;
            o[SP] += hi;
        }
    }
}

// ---------------------------------------------------------------------------

extern "C" void kernel_launch(void* const* d_in, const int* in_sizes, int n_in,
                              void* d_out, int out_size) {
    (void)in_sizes; (void)n_in; (void)out_size;
    const float* A    = (const float*)d_in[0];   // attention [1,1072,8,64,64]
    const float* V    = (const float*)d_in[1];   // value [1,256,8,64,64]
    const float* Wm   = (const float*)d_in[2];   // conv_w [256,256]
    const float* bias = (const float*)d_in[3];   // conv_b [256]
    float* out = (float*)d_out;

    const int SMEM_HW = 16 * 64 * 16 * (int)sizeof(float2);  // 131072

    cudaFuncSetAttribute(attn_h_kernel, cudaFuncAttributeMaxDynamicSharedMemorySize, SMEM_HW);
    cudaFuncSetAttribute(attn_w_kernel, cudaFuncAttributeMaxDynamicSharedMemorySize, SMEM_HW);

    conv_gemm_kernel<<<dim3(SP / 256, CDIM / 32), 256>>>(V, Wm, bias);
    attn_t_kernel<<<dim3(PLANE / 128, HEADS), 512>>>(A, out);
    attn_h_kernel<<<dim3(4, TT, HEADS), 512, SMEM_HW>>>(A, out);
    attn_w_kernel<<<dim3(4, TT, HEADS), 512, SMEM_HW>>>(A, out);
}

// round 3
// speedup vs baseline: 1.1658x; 1.1495x over previous
#include <cuda_runtime.h>
#include <cstdint>

// Problem constants (n=1, C=256, t=8, h=64, w=64, heads=8)
#define HEADS 8
#define TT 8
#define HH 64
#define WW 64
#define SDIM (TT + HH + WW - 2)   // 134
#define SP (TT * HH * WW)          // 32768
#define PLANE (HH * WW)            // 4096
#define CDIM 256
#define CG (CDIM / HEADS)          // 32 channels per head

// Scratch for pv = conv(value)
__device__ float g_pv[CDIM * SP];

using ull = unsigned long long;

__device__ __forceinline__ ull packf2(float lo, float hi) {
    ull r;
    asm("mov.b64 %0, {%1, %2};" : "=l"(r) : "f"(lo), "f"(hi));
    return r;
}
__device__ __forceinline__ void unpackf2(ull v, float& lo, float& hi) {
    asm("mov.b64 {%0, %1}, %2;" : "=f"(lo), "=f"(hi) : "l"(v));
}
__device__ __forceinline__ void ffma2(ull& d, ull a, ull b) {
    asm("fma.rn.f32x2 %0, %1, %2, %3;" : "=l"(d) : "l"(a), "l"(b), "l"(d));
}

// ---------------------------------------------------------------------------
// Kernel 1: pv[o, s] = bias[o] + sum_c W[o, c] * V[c, s]
// ---------------------------------------------------------------------------
__global__ void __launch_bounds__(256) conv_gemm_kernel(
    const float* __restrict__ V, const float* __restrict__ Wm,
    const float* __restrict__ bias)
{
    __shared__ float2 Ws2[16][32];  // [k][o], duplicated
    __shared__ float Vs[16][256];   // [k][s]

    const int tid = threadIdx.x;
    const int tx = tid & 31;
    const int ty = tid >> 5;
    const int oBase = blockIdx.y * 32;
    const int sBase = blockIdx.x * 256;

    ull acc[4][4];
    #pragma unroll
    for (int i = 0; i < 4; ++i) {
        float bv = bias[oBase + ty * 4 + i];
        ull pb = packf2(bv, bv);
        #pragma unroll
        for (int j = 0; j < 4; ++j) acc[i][j] = pb;
    }

    float4 wv;
    float4 vv[4];
    const int oo = tid >> 2;
    const int kb = (tid & 3) * 4;

    if (tid < 128) wv = *(const float4*)&Wm[(oBase + oo) * CDIM + 0 + kb];
    #pragma unroll
    for (int j = 0; j < 4; ++j) {
        int idx = tid + j * 256;
        int r = idx >> 6, c4 = idx & 63;
        vv[j] = *(const float4*)&V[(0 + r) * SP + sBase + c4 * 4];
    }

    for (int kk = 0; kk < CDIM; kk += 16) {
        __syncthreads();
        if (tid < 128) {
            Ws2[kb + 0][oo] = make_float2(wv.x, wv.x);
            Ws2[kb + 1][oo] = make_float2(wv.y, wv.y);
            Ws2[kb + 2][oo] = make_float2(wv.z, wv.z);
            Ws2[kb + 3][oo] = make_float2(wv.w, wv.w);
        }
        #pragma unroll
        for (int j = 0; j < 4; ++j) {
            int idx = tid + j * 256;
            int r = idx >> 6, c4 = idx & 63;
            *(float4*)&Vs[r][c4 * 4] = vv[j];
        }
        __syncthreads();

        int kn = kk + 16;
        if (kn < CDIM) {
            if (tid < 128) wv = *(const float4*)&Wm[(oBase + oo) * CDIM + kn + kb];
            #pragma unroll
            for (int j = 0; j < 4; ++j) {
                int idx = tid + j * 256;
                int r = idx >> 6, c4 = idx & 63;
                vv[j] = *(const float4*)&V[(kn + r) * SP + sBase + c4 * 4];
            }
        }

        #pragma unroll
        for (int k = 0; k < 16; ++k) {
            float4 b0 = *(const float4*)&Vs[k][tx * 4];
            float4 b1 = *(const float4*)&Vs[k][128 + tx * 4];
            ull bb0 = packf2(b0.x, b0.y);
            ull bb1 = packf2(b0.z, b0.w);
            ull bb2 = packf2(b1.x, b1.y);
            ull bb3 = packf2(b1.z, b1.w);
            #pragma unroll
            for (int i = 0; i < 4; ++i) {
                ull a2 = *reinterpret_cast<const ull*>(&Ws2[k][ty * 4 + i]);
                ffma2(acc[i][0], a2, bb0);
                ffma2(acc[i][1], a2, bb1);
                ffma2(acc[i][2], a2, bb2);
                ffma2(acc[i][3], a2, bb3);
            }
        }
    }

    #pragma unroll
    for (int i = 0; i < 4; ++i) {
        float r0, r1, r2, r3, r4, r5, r6, r7;
        unpackf2(acc[i][0], r0, r1);
        unpackf2(acc[i][1], r2, r3);
        unpackf2(acc[i][2], r4, r5);
        unpackf2(acc[i][3], r6, r7);
        float* dst = &g_pv[(oBase + ty * 4 + i) * SP + sBase];
        float4 v0 = {r0, r1, r2, r3};
        float4 v1 = {r4, r5, r6, r7};
        *(float4*)&dst[tx * 4] = v0;
        *(float4*)&dst[128 + tx * 4] = v1;
    }
}

// ---------------------------------------------------------------------------
// Kernel 2: t-sum. out[c,tau,pos] = sum_s A_t[s,tau,pos] * pv[c,s,pos]
// ---------------------------------------------------------------------------
__global__ void __launch_bounds__(512) attn_t_kernel(
    const float* __restrict__ A, float* __restrict__ out)
{
    __shared__ float ats[8 * 8 * 128];

    const int tid = threadIdx.x;
    const int pos = tid & 127;
    const int cg = tid >> 7;
    const int pos0 = blockIdx.x * 128;
    const int b = blockIdx.y;
    const int cbase = b * CG;
    const int attb = b * SDIM * SP;

    for (int i = tid; i < 8192; i += 512) {
        int p_i = i & 127, tau_i = (i >> 7) & 7, s_i = i >> 10;
        ats[i] = A[attb + s_i * SP + tau_i * PLANE + pos0 + p_i];
    }

    ull pvr[8][4];
    #pragma unroll
    for (int s = 0; s < 8; ++s)
        #pragma unroll
        for (int cp = 0; cp < 4; ++cp) {
            const float* g = &g_pv[(cbase + cg * 8 + 2 * cp) * SP + s * PLANE + pos0 + pos];
            pvr[s][cp] = packf2(g[0], g[SP]);
        }
    __syncthreads();

    ull z = packf2(0.0f, 0.0f);
    #pragma unroll 1
    for (int tau = 0; tau < 8; ++tau) {
        ull acc[4] = {z, z, z, z};
        #pragma unroll
        for (int s = 0; s < 8; ++s) {
            float at = ats[(s * 8 + tau) * 128 + pos];
            ull a2 = packf2(at, at);
            #pragma unroll
            for (int cp = 0; cp < 4; ++cp)
                ffma2(acc[cp], a2, pvr[s][cp]);
        }
        #pragma unroll
        for (int cp = 0; cp < 4; ++cp) {
            float lo, hi;
            unpackf2(acc[cp], lo, hi);
            float* o = &out[(cbase + cg * 8 + 2 * cp) * SP + tau * PLANE + pos0 + pos];
            o[0] = lo;
            o[SP] = hi;
        }
    }
}

// ---------------------------------------------------------------------------
// Kernel 3: h-sum, RMW into out.  out[c,tau,q,x] += sum_{p!=q} Ah[j(p,q)]*pv[c,tau,p,x]
// p-iteration, per-qi pointer walk (advance unless p==q), include bogus p==q
// term and subtract it exactly in the epilogue.
// Block: (x-tile 16, tau, head). 512 threads.
// Thread: xq=tid&3 (x=4xq+k), qg=(tid>>2)&15 (q=4qg+qi), cg=tid>>6 (channels 4cg..+3)
// smem: pvh2[64p][16cp2][16x] float2 = 128KB (channel pairs)
// ---------------------------------------------------------------------------
__global__ void __launch_bounds__(512) attn_h_kernel(
    const float* __restrict__ A, float* __restrict__ out)
{
    extern __shared__ float2 pvh2[];   // [p][cp2][x] : 64*16*16 float2 = 128KB

    const int tid = threadIdx.x;
    const int xq = tid & 3;
    const int qg = (tid >> 2) & 15;
    const int cg = tid >> 6;            // 0..7
    const int x0 = blockIdx.x * 16;
    const int tau = blockIdx.y;
    const int b = blockIdx.z;
    const int cbase = b * CG;
    const int attb = b * SDIM * SP;

    // load pv: [p][cp2][x]
    for (int i = tid; i < 16384; i += 512) {
        int x = i & 15, p = (i >> 4) & 63, cp2 = i >> 10;
        const float* g = &g_pv[(cbase + 2 * cp2) * SP + tau * PLANE + p * 64 + x0 + x];
        pvh2[(p * 16 + cp2) * 16 + x] = make_float2(g[0], g[SP]);
    }
    __syncthreads();

    ull z = packf2(0.0f, 0.0f);
    ull acc[4][4][2];   // [qi][k][r]  channels (4cg+2r, 4cg+2r+1), x=4xq+k
    #pragma unroll
    for (int qi = 0; qi < 4; ++qi)
        #pragma unroll
        for (int k = 0; k < 4; ++k) { acc[qi][k][0] = z; acc[qi][k][1] = z; }

    const float* Ahb = A + attb + TT * SP + tau * PLANE;
    int qv[4];
    const float* pA[4];
    #pragma unroll
    for (int qi = 0; qi < 4; ++qi) {
        qv[qi] = 4 * qg + qi;
        pA[qi] = Ahb + qv[qi] * 64 + x0 + 4 * xq;   // j=0 row
    }

    #pragma unroll 2
    for (int p = 0; p < 64; ++p) {
        float4 av[4];
        #pragma unroll
        for (int qi = 0; qi < 4; ++qi)
            av[qi] = __ldg((const float4*)pA[qi]);
        #pragma unroll
        for (int qi = 0; qi < 4; ++qi)
            pA[qi] += (p != qv[qi]) ? SP : 0;

        ull pp[4][2];
        #pragma unroll
        for (int k = 0; k < 4; ++k) {
            pp[k][0] = *reinterpret_cast<const ull*>(&pvh2[(p * 16 + 2 * cg + 0) * 16 + 4 * xq + k]);
            pp[k][1] = *reinterpret_cast<const ull*>(&pvh2[(p * 16 + 2 * cg + 1) * 16 + 4 * xq + k]);
        }
        #pragma unroll
        for (int qi = 0; qi < 4; ++qi) {
            float a0 = av[qi].x, a1 = av[qi].y, a2v = av[qi].z, a3 = av[qi].w;
            ull b0 = packf2(a0, a0), b1 = packf2(a1, a1);
            ull b2 = packf2(a2v, a2v), b3 = packf2(a3, a3);
            ffma2(acc[qi][0][0], b0, pp[0][0]); ffma2(acc[qi][0][1], b0, pp[0][1]);
            ffma2(acc[qi][1][0], b1, pp[1][0]); ffma2(acc[qi][1][1], b1, pp[1][1]);
            ffma2(acc[qi][2][0], b2, pp[2][0]); ffma2(acc[qi][2][1], b2, pp[2][1]);
            ffma2(acc[qi][3][0], b3, pp[3][0]); ffma2(acc[qi][3][1], b3, pp[3][1]);
        }
    }

    // subtract the bogus p==q term: A row j=q at this (q, x) times pv[p=q]
    #pragma unroll
    for (int qi = 0; qi < 4; ++qi) {
        int q = qv[qi];
        float4 bv = __ldg((const float4*)&Ahb[q * SP + q * 64 + x0 + 4 * xq]);
        float bs[4] = {bv.x, bv.y, bv.z, bv.w};
        #pragma unroll
        for (int k = 0; k < 4; ++k) {
            ull nb = packf2(-bs[k], -bs[k]);
            ull p0 = *reinterpret_cast<const ull*>(&pvh2[(q * 16 + 2 * cg + 0) * 16 + 4 * xq + k]);
            ull p1 = *reinterpret_cast<const ull*>(&pvh2[(q * 16 + 2 * cg + 1) * 16 + 4 * xq + k]);
            ffma2(acc[qi][k][0], nb, p0);
            ffma2(acc[qi][k][1], nb, p1);
        }
    }

    // RMW store: per (qi, r, half-of-pair): float4 over k
    #pragma unroll
    for (int qi = 0; qi < 4; ++qi) {
        int q = qv[qi];
        #pragma unroll
        for (int r = 0; r < 2; ++r) {
            float lo[4], hi[4];
            #pragma unroll
            for (int k = 0; k < 4; ++k) unpackf2(acc[qi][k][r], lo[k], hi[k]);
            float* o0 = &out[(cbase + 4 * cg + 2 * r) * SP + tau * PLANE + q * 64 + x0 + 4 * xq];
            float* o1 = o0 + SP;
            float4 t0 = *(float4*)o0;
            float4 t1 = *(float4*)o1;
            t0.x += lo[0]; t0.y += lo[1]; t0.z += lo[2]; t0.w += lo[3];
            t1.x += hi[0]; t1.y += hi[1]; t1.z += hi[2]; t1.w += hi[3];
            *(float4*)o0 = t0;
            *(float4*)o1 = t1;
        }
    }
}

// ---------------------------------------------------------------------------
// Kernel 4: w-sum, RMW into out. j-space: out[c,q,x] += sum_j Aw[j]*pv[c,q,j+(j>=x)]
// Block: (q-tile 16, tau, head). 512 threads.
// Thread: xo=tid&7 (x=8xo+m), cg=(tid>>3)&3 (channels 8cg..+7), qloc=tid>>5
// smem: pvw2[16q][64p][18cp2pad] float2 = 144KB
// Main loop uses uniform p = j + (j >= 8xo+7); mismatches corrected in epilogue.
// ---------------------------------------------------------------------------
__global__ void __launch_bounds__(512) attn_w_kernel(
    const float* __restrict__ A, float* __restrict__ out)
{
    extern __shared__ float2 pvw2[];   // [q][p][18] : 16*64*18 float2 = 144KB

    const int tid = threadIdx.x;
    const int xo = tid & 7;
    const int cg = (tid >> 3) & 3;
    const int qloc = tid >> 5;          // 0..15
    const int q0 = blockIdx.x * 16;
    const int tau = blockIdx.y;
    const int b = blockIdx.z;
    const int cbase = b * CG;
    const int attb = b * SDIM * SP;
    const int q = q0 + qloc;

    // load pv: [q][p][18cp2]
    for (int i = tid; i < 16384; i += 512) {
        int p = i & 63, qi = (i >> 6) & 15, cp2 = i >> 10;
        const float* g = &g_pv[(cbase + 2 * cp2) * SP + tau * PLANE + (q0 + qi) * 64 + p];
        pvw2[(qi * 64 + p) * 18 + cp2] = make_float2(g[0], g[SP]);
    }
    __syncthreads();

    ull z = packf2(0.0f, 0.0f);
    ull acc[8][4];     // [m (x=8xo+m)][cp]  channels (8cg+2cp, 8cg+2cp+1)
    #pragma unroll
    for (int m = 0; m < 8; ++m)
        #pragma unroll
        for (int cp = 0; cp < 4; ++cp) acc[m][cp] = z;

    const float* Awb = A + attb + (TT + HH - 1) * SP + tau * PLANE + q * 64;
    const float* pA = Awb + 8 * xo;
    const int thr = 8 * xo + 7;

    #pragma unroll 4
    for (int j = 0; j < 63; ++j) {
        float4 av0 = __ldg((const float4*)pA);
        float4 av1 = __ldg((const float4*)(pA + 4));
        pA += SP;
        int p = j + (j >= thr ? 1 : 0);

        const ull* u = reinterpret_cast<const ull*>(&pvw2[(qloc * 64 + p) * 18 + 4 * cg]);
        ull pp0 = u[0], pp1 = u[1], pp2 = u[2], pp3 = u[3];

        float a[8] = {av0.x, av0.y, av0.z, av0.w, av1.x, av1.y, av1.z, av1.w};
        #pragma unroll
        for (int m = 0; m < 8; ++m) {
            ull am = packf2(a[m], a[m]);
            ffma2(acc[m][0], am, pp0);
            ffma2(acc[m][1], am, pp1);
            ffma2(acc[m][2], am, pp2);
            ffma2(acc[m][3], am, pp3);
        }
    }

    // corrections: for j = 8xo+jj (jj 0..6), lanes m <= jj used pv[j] but need pv[j+1]
    #pragma unroll 1
    for (int jj = 0; jj < 7; ++jj) {
        int j = 8 * xo + jj;
        const ull* uj  = reinterpret_cast<const ull*>(&pvw2[(qloc * 64 + j) * 18 + 4 * cg]);
        const ull* uj1 = reinterpret_cast<const ull*>(&pvw2[(qloc * 64 + j + 1) * 18 + 4 * cg]);
        ull pj0 = uj[0], pj1 = uj[1], pj2 = uj[2], pj3 = uj[3];
        ull q0_ = uj1[0], q1_ = uj1[1], q2_ = uj1[2], q3_ = uj1[3];
        for (int m = 0; m <= jj; ++m) {
            float bb = __ldg(&Awb[j * SP + 8 * xo + m]);
            ull b2 = packf2(bb, bb);
            ull nb2 = packf2(-bb, -bb);
            ffma2(acc[m][0], b2, q0_); ffma2(acc[m][0], nb2, pj0);
            ffma2(acc[m][1], b2, q1_); ffma2(acc[m][1], nb2, pj1);
            ffma2(acc[m][2], b2, q2_); ffma2(acc[m][2], nb2, pj2);
            ffma2(acc[m][3], b2, q3_); ffma2(acc[m][3], nb2, pj3);
        }
    }

    // RMW store: per (cp, half): two float4 over m
    #pragma unroll
    for (int cp = 0; cp < 4; ++cp) {
        float lo[8], hi[8];
        #pragma unroll
        for (int m = 0; m < 8; ++m) unpackf2(acc[m][cp], lo[m], hi[m]);
        float* o0 = &out[(cbase + 8 * cg + 2 * cp) * SP + tau * PLANE + q * 64 + 8 * xo];
        float* o1 = o0 + SP;
        float4 a0 = *(float4*)o0;          float4 a1 = *(float4*)(o0 + 4);
        float4 b0v = *(float4*)o1;         float4 b1v = *(float4*)(o1 + 4);
        a0.x += lo[0]; a0.y += lo[1]; a0.z += lo[2]; a0.w += lo[3];
        a1.x += lo[4]; a1.y += lo[5]; a1.z += lo[6]; a1.w += lo[7];
        b0v.x += hi[0]; b0v.y += hi[1]; b0v.z += hi[2]; b0v.w += hi[3];
        b1v.x += hi[4]; b1v.y += hi[5]; b1v.z += hi[6]; b1v.w += hi[7];
        *(float4*)o0 = a0;       *(float4*)(o0 + 4) = a1;
        *(float4*)o1 = b0v;      *(float4*)(o1 + 4) = b1v;
    }
}

// ---------------------------------------------------------------------------

extern "C" void kernel_launch(void* const* d_in, const int* in_sizes, int n_in,
                              void* d_out, int out_size) {
    (void)in_sizes; (void)n_in; (void)out_size;
    const float* A    = (const float*)d_in[0];
    const float* V    = (const float*)d_in[1];
    const float* Wm   = (const float*)d_in[2];
    const float* bias = (const float*)d_in[3];
    float* out = (float*)d_out;

    const int SMEM_H = 64 * 16 * 16 * (int)sizeof(float2);   // 131072
    const int SMEM_W = 16 * 64 * 18 * (int)sizeof(float2);   // 147456

    cudaFuncSetAttribute(attn_h_kernel, cudaFuncAttributeMaxDynamicSharedMemorySize, SMEM_H);
    cudaFuncSetAttribute(attn_w_kernel, cudaFuncAttributeMaxDynamicSharedMemorySize, SMEM_W);

    conv_gemm_kernel<<<dim3(SP / 256, CDIM / 32), 256>>>(V, Wm, bias);
    attn_t_kernel<<<dim3(PLANE / 128, HEADS), 512>>>(A, out);
    attn_h_kernel<<<dim3(4, TT, HEADS), 512, SMEM_H>>>(A, out);
    attn_w_kernel<<<dim3(4, TT, HEADS), 512, SMEM_W>>>(A, out);
}